// round 1
// baseline (speedup 1.0000x reference)
#include <cuda_runtime.h>

#define N_PTS 200000
#define CDIM 96
#define FDIM 96
#define NCOLS 3
#define HDIM 288          // NCOLS * FDIM
#define EPSV 1e-3f

// ---------------- scratch (device globals: no allocation allowed) ----------
__device__ float g_Z [(size_t)N_PTS * HDIM];   // stage-1 GEMM out (230 MB)
__device__ float g_h [(size_t)N_PTS * HDIM];   // hidden after assemble1
__device__ float g_Zh[(size_t)N_PTS * HDIM];   // stage-2 GEMM out
__device__ int   g_prev[NCOLS * N_PTS];
__device__ int   g_next[NCOLS * N_PTS];
__device__ float g_B1[CDIM * HDIM];            // packed W1 -> [k_in][n] row-major
__device__ float g_B2[HDIM * HDIM];            // packed W2 -> [k_in][n] row-major

// ---------------- pack weights into GEMM-friendly [K][N] layout ------------
// B[kk, n] with n = tap*FDIM + f ;  W1:(3,96,96)  W2:(3,288,96)
__global__ void pack_w_kernel(const float* __restrict__ W1,
                              const float* __restrict__ W2) {
    int t = blockIdx.x * blockDim.x + threadIdx.x;
    if (t < CDIM * HDIM) {
        int kk = t / HDIM, n = t % HDIM;
        int tap = n / FDIM, f = n % FDIM;
        g_B1[t] = W1[((size_t)tap * CDIM + kk) * FDIM + f];
    }
    if (t < HDIM * HDIM) {
        int kk = t / HDIM, n = t % HDIM;
        int tap = n / FDIM, f = n % FDIM;
        g_B2[t] = W2[((size_t)tap * HDIM + kk) * FDIM + f];
    }
}

// ---------------- neighbor maps:  p = idx_c[i]  ->  idx_c[i-1], idx_c[i+1] -
__global__ void prevnext_kernel(const int* __restrict__ index) {
    int t = blockIdx.x * blockDim.x + threadIdx.x;
    if (t >= NCOLS * N_PTS) return;
    int i = t / NCOLS;
    int c = t % NCOLS;
    int p = index[t];
    g_prev[c * N_PTS + p] = (i > 0)         ? index[t - NCOLS] : -1;
    g_next[c * N_PTS + p] = (i < N_PTS - 1) ? index[t + NCOLS] : -1;
}

// ---------------- tiled SGEMM:  C[M,288] = A[M,KDIM] @ B[KDIM,288] ---------
// BM=128, BN=96, BK=16, 256 threads, 8x6 micro-tile per thread.
// STAGE 1: A = X (param), B = g_B1, C = g_Z,  KDIM = 96
// STAGE 2: A = g_h,       B = g_B2, C = g_Zh, KDIM = 288
template <int STAGE>
__global__ __launch_bounds__(256)
void sgemm_kernel(const float* __restrict__ Aext, int M) {
    constexpr int KDIM = (STAGE == 1) ? CDIM : HDIM;
    const float* __restrict__ A = (STAGE == 1) ? Aext : g_h;
    const float* __restrict__ B = (STAGE == 1) ? g_B1 : g_B2;
    float* __restrict__       C = (STAGE == 1) ? g_Z  : g_Zh;

    constexpr int BM = 128, BN = 96, BK = 16;
    __shared__ float As[BK][BM + 4];   // +4 pad: break 128-stride bank conflicts
    __shared__ float Bs[BK][BN];

    int tid  = threadIdx.x;
    int tx   = tid & 15;        // 0..15 -> 6 cols each
    int ty   = tid >> 4;        // 0..15 -> 8 rows each
    int row0 = blockIdx.x * BM;
    int col0 = blockIdx.y * BN;

    int arow = tid >> 1;            // 0..127 : A-row loaded by this thread
    int ak4  = (tid & 1) * 2;       // float4 slot (0 or 2) within BK=16

    float acc[8][6];
    #pragma unroll
    for (int m = 0; m < 8; m++)
        #pragma unroll
        for (int n = 0; n < 6; n++) acc[m][n] = 0.f;

    for (int k0 = 0; k0 < KDIM; k0 += BK) {
        // stage A tile (transposed into smem)
        {
            int gr = row0 + arow;
            float4 v0 = make_float4(0, 0, 0, 0), v1 = v0;
            if (gr < M) {
                const float4* Ap =
                    reinterpret_cast<const float4*>(A + (size_t)gr * KDIM + k0);
                v0 = Ap[ak4];
                v1 = Ap[ak4 + 1];
            }
            int kb = ak4 * 4;
            As[kb + 0][arow] = v0.x; As[kb + 1][arow] = v0.y;
            As[kb + 2][arow] = v0.z; As[kb + 3][arow] = v0.w;
            As[kb + 4][arow] = v1.x; As[kb + 5][arow] = v1.y;
            As[kb + 6][arow] = v1.z; As[kb + 7][arow] = v1.w;
        }
        // stage B tile (tiny, L2-hot)
        #pragma unroll
        for (int i = 0; i < (BK * BN) / 256; i++) {
            int idx = tid + i * 256;
            int kk = idx / BN, n = idx % BN;
            Bs[kk][n] = B[(size_t)(k0 + kk) * HDIM + col0 + n];
        }
        __syncthreads();

        #pragma unroll
        for (int kk = 0; kk < BK; kk++) {
            float a[8], b[6];
            #pragma unroll
            for (int m = 0; m < 8; m++) a[m] = As[kk][ty * 8 + m];
            #pragma unroll
            for (int n = 0; n < 6; n++) b[n] = Bs[kk][tx * 6 + n];
            #pragma unroll
            for (int m = 0; m < 8; m++)
                #pragma unroll
                for (int n = 0; n < 6; n++)
                    acc[m][n] = fmaf(a[m], b[n], acc[m][n]);
        }
        __syncthreads();
    }

    #pragma unroll
    for (int m = 0; m < 8; m++) {
        int gr = row0 + ty * 8 + m;
        if (gr < M) {
            float* Cp = C + (size_t)gr * HDIM + col0 + tx * 6;
            #pragma unroll
            for (int n = 0; n < 6; n++) Cp[n] = acc[m][n];
        }
    }
}

// ---------------- assemble stage 1:  h = relu(b1 + 3 gathered taps) --------
__global__ __launch_bounds__(HDIM)
void assemble1_kernel(const float* __restrict__ b1) {
    int p  = blockIdx.x;
    int f  = threadIdx.x;          // 0..287
    int c  = f / FDIM;
    int ff = f - c * FDIM;
    int prev = g_prev[c * N_PTS + p];
    int next = g_next[c * N_PTS + p];
    float v = b1[ff];
    if (prev >= 0) v += g_Z[(size_t)prev * HDIM + ff];
    v += g_Z[(size_t)p * HDIM + FDIM + ff];
    if (next >= 0) v += g_Z[(size_t)next * HDIM + 2 * FDIM + ff];
    g_h[(size_t)p * HDIM + f] = fmaxf(v, 0.f);
}

// ------- assemble stage 2 + residual + layernorm + store output ------------
__global__ __launch_bounds__(HDIM)
void assemble2_ln_kernel(const float* __restrict__ b2,
                         const float* __restrict__ gamma,
                         const float* __restrict__ beta,
                         float* __restrict__ out) {
    __shared__ float s_sum[9], s_sq[9];
    int p  = blockIdx.x;
    int f  = threadIdx.x;
    int c  = f / FDIM;
    int ff = f - c * FDIM;
    int prev = g_prev[c * N_PTS + p];
    int next = g_next[c * N_PTS + p];
    float v = b2[ff];
    if (prev >= 0) v += g_Zh[(size_t)prev * HDIM + ff];
    v += g_Zh[(size_t)p * HDIM + FDIM + ff];
    if (next >= 0) v += g_Zh[(size_t)next * HDIM + 2 * FDIM + ff];
    float x = g_h[(size_t)p * HDIM + f] + fmaxf(v, 0.f);

    // block-wide mean / var over 288
    float s = x, q = x * x;
    #pragma unroll
    for (int o = 16; o > 0; o >>= 1) {
        s += __shfl_down_sync(0xffffffffu, s, o);
        q += __shfl_down_sync(0xffffffffu, q, o);
    }
    int w = f >> 5, l = f & 31;
    if (l == 0) { s_sum[w] = s; s_sq[w] = q; }
    __syncthreads();
    float ts = 0.f, tq = 0.f;
    #pragma unroll
    for (int i = 0; i < 9; i++) { ts += s_sum[i]; tq += s_sq[i]; }
    float mu  = ts * (1.f / HDIM);
    float var = tq * (1.f / HDIM) - mu * mu;
    float r   = rsqrtf(var + EPSV);
    out[(size_t)p * HDIM + f] = (x - mu) * r * gamma[f] + beta[f];
}

// ---------------- index pass-through tail (second tuple element) -----------
__global__ void copy_index_kernel(const int* __restrict__ index,
                                  float* __restrict__ out, int count) {
    int t = blockIdx.x * blockDim.x + threadIdx.x;
    if (t < count) out[t] = (float)index[t];
}

// ---------------------------------------------------------------------------
extern "C" void kernel_launch(void* const* d_in, const int* in_sizes, int n_in,
                              void* d_out, int out_size) {
    const float* X     = (const float*)d_in[0];
    const int*   index = (const int*)  d_in[1];
    const float* W1    = (const float*)d_in[2];
    const float* b1    = (const float*)d_in[3];
    const float* W2    = (const float*)d_in[4];
    const float* b2    = (const float*)d_in[5];
    const float* gamma = (const float*)d_in[6];
    const float* beta  = (const float*)d_in[7];
    float* out = (float*)d_out;

    pack_w_kernel<<<(HDIM * HDIM + 255) / 256, 256>>>(W1, W2);
    prevnext_kernel<<<(NCOLS * N_PTS + 255) / 256, 256>>>(index);

    dim3 gemm_grid((N_PTS + 127) / 128, HDIM / 96);
    sgemm_kernel<1><<<gemm_grid, 256>>>(X, N_PTS);            // Z  = X @ B1
    assemble1_kernel<<<N_PTS, HDIM>>>(b1);                    // h
    sgemm_kernel<2><<<gemm_grid, 256>>>(nullptr, N_PTS);      // Zh = h @ B2
    assemble2_ln_kernel<<<N_PTS, HDIM>>>(b2, gamma, beta, out);

    int tail = out_size - N_PTS * HDIM;                       // index tuple element
    if (tail > 0) {
        if (tail > NCOLS * N_PTS) tail = NCOLS * N_PTS;
        copy_index_kernel<<<(tail + 255) / 256, 256>>>(
            index, out + (size_t)N_PTS * HDIM, tail);
    }
}

// round 3
// speedup vs baseline: 2.3853x; 2.3853x over previous
#include <cuda_runtime.h>
#include <cuda_bf16.h>
#include <cstdint>

#define N_PTS 200000
#define CDIM 96
#define FDIM 96
#define NCOLS 3
#define HDIM 288          // NCOLS * FDIM
#define EPSV 1e-3f

// ---------------- scratch (device globals: no allocation allowed) ----------
__device__ float g_Z [(size_t)N_PTS * HDIM];   // stage-1 GEMM out
__device__ float g_h [(size_t)N_PTS * HDIM];   // hidden after assemble1
__device__ float g_Zh[(size_t)N_PTS * HDIM];   // stage-2 GEMM out
__device__ int   g_prev[NCOLS * N_PTS];
__device__ int   g_next[NCOLS * N_PTS];
// bf16-split weights, MMA layout: B[n][k]  (n = tap*FDIM + f, k = input chan)
__device__ __nv_bfloat16 g_B1h[HDIM * CDIM];
__device__ __nv_bfloat16 g_B1l[HDIM * CDIM];
__device__ __nv_bfloat16 g_B2h[HDIM * HDIM];
__device__ __nv_bfloat16 g_B2l[HDIM * HDIM];

// ======================= helpers ==========================================
__device__ __forceinline__ uint32_t smem_u32(const void* p) {
    uint32_t a;
    asm("{ .reg .u64 t; cvta.to.shared.u64 t, %1; cvt.u32.u64 %0, t; }"
        : "=r"(a) : "l"(p));
    return a;
}
__device__ __forceinline__ void cp16(uint32_t dst, const void* src, uint32_t sz) {
    asm volatile("cp.async.ca.shared.global [%0], [%1], 16, %2;"
                 :: "r"(dst), "l"(src), "r"(sz) : "memory");
}
__device__ __forceinline__ void cp8(uint32_t dst, const void* src) {
    asm volatile("cp.async.ca.shared.global [%0], [%1], 8;"
                 :: "r"(dst), "l"(src) : "memory");
}
#define CP_COMMIT() asm volatile("cp.async.commit_group;" ::: "memory")

// D += A*B  (m16n8k16, bf16 in, fp32 acc)
__device__ __forceinline__ void mma_bf16(float* d, const uint32_t* a,
                                         const uint32_t* b) {
    asm volatile(
        "mma.sync.aligned.m16n8k16.row.col.f32.bf16.bf16.f32 "
        "{%0,%1,%2,%3}, {%4,%5,%6,%7}, {%8,%9}, {%0,%1,%2,%3};"
        : "+f"(d[0]), "+f"(d[1]), "+f"(d[2]), "+f"(d[3])
        : "r"(a[0]), "r"(a[1]), "r"(a[2]), "r"(a[3]), "r"(b[0]), "r"(b[1]));
}

// fp32 pair -> bf16x2 hi + bf16x2 lo (residual)
__device__ __forceinline__ void split2(float2 v, uint32_t& hi, uint32_t& lo) {
    uint32_t h;
    asm("cvt.rn.bf16x2.f32 %0, %1, %2;" : "=r"(h) : "f"(v.y), "f"(v.x));
    float hx = __uint_as_float(h << 16);
    float hy = __uint_as_float(h & 0xFFFF0000u);
    float rx = v.x - hx, ry = v.y - hy;
    uint32_t l;
    asm("cvt.rn.bf16x2.f32 %0, %1, %2;" : "=r"(l) : "f"(ry), "f"(rx));
    hi = h; lo = l;
}

// ---------------- pack weights: bf16 hi/lo split, [n][k] MMA layout --------
__global__ void pack_w_kernel(const float* __restrict__ W1,
                              const float* __restrict__ W2) {
    int t = blockIdx.x * blockDim.x + threadIdx.x;
    if (t < HDIM * HDIM) {                       // W2: (3, 288, 96)
        int n = t / HDIM, k = t % HDIM;
        int tap = n / FDIM, f = n % FDIM;
        float w = W2[((size_t)tap * HDIM + k) * FDIM + f];
        __nv_bfloat16 hi = __float2bfloat16_rn(w);
        g_B2h[(size_t)n * HDIM + k] = hi;
        g_B2l[(size_t)n * HDIM + k] = __float2bfloat16_rn(w - __bfloat162float(hi));
    }
    if (t < HDIM * CDIM) {                       // W1: (3, 96, 96)
        int n = t / CDIM, k = t % CDIM;
        int tap = n / FDIM, f = n % FDIM;
        float w = W1[((size_t)tap * CDIM + k) * FDIM + f];
        __nv_bfloat16 hi = __float2bfloat16_rn(w);
        g_B1h[(size_t)n * CDIM + k] = hi;
        g_B1l[(size_t)n * CDIM + k] = __float2bfloat16_rn(w - __bfloat162float(hi));
    }
}

// ---------------- neighbor maps --------------------------------------------
__global__ void prevnext_kernel(const int* __restrict__ index) {
    int t = blockIdx.x * blockDim.x + threadIdx.x;
    if (t >= NCOLS * N_PTS) return;
    int i = t / NCOLS;
    int c = t % NCOLS;
    int p = index[t];
    g_prev[c * N_PTS + p] = (i > 0)         ? index[t - NCOLS] : -1;
    g_next[c * N_PTS + p] = (i < N_PTS - 1) ? index[t + NCOLS] : -1;
}

// ============== split-bf16 HMMA GEMM:  C[M,288] = A[M,K] @ B[288,K]^T ======
// CTA: BM=128, BN=96, BK=32. 8 warps as 4(M) x 2(N); warp tile 32x48.
// smem layout (bytes):
//   As  fp32 [2][128][36]            : [0, 36864)
//   Bh  bf16 [2][96][36]             : [36864, 50688)
//   Bl  bf16 [2][96][36]             : [50688, 64512)
#define GSM_TOTAL 64512

template <int KDIM>
__device__ __forceinline__ void gemm_stage(
        int tid, int row0, int col0, int k0, int buf,
        const float* __restrict__ Ap,
        const __nv_bfloat16* __restrict__ Bhp,
        const __nv_bfloat16* __restrict__ Blp,
        uint32_t sb) {
    uint32_t abase = sb + buf * 18432;
    #pragma unroll
    for (int i = 0; i < 4; i++) {
        int cid = tid + i * 256;
        int r = cid >> 3, c16 = cid & 7;
        int gr = row0 + r;
        cp16(abase + (uint32_t)(r * 144 + c16 * 16),
             Ap + (size_t)gr * KDIM + k0 + c16 * 4,
             gr < N_PTS ? 16u : 0u);
    }
    uint32_t bhb = sb + 36864 + buf * 6912;
    uint32_t blb = sb + 50688 + buf * 6912;
    #pragma unroll
    for (int i = 0; i < 3; i++) {
        int cid = tid + i * 256;
        int r = cid >> 3, c8 = cid & 7;
        size_t go = (size_t)(col0 + r) * KDIM + k0 + c8 * 4;
        cp8(bhb + (uint32_t)(r * 72 + c8 * 8), Bhp + go);
        cp8(blb + (uint32_t)(r * 72 + c8 * 8), Blp + go);
    }
}

template <int STAGE>
__global__ __launch_bounds__(256, 2)
void mma_gemm_kernel(const float* __restrict__ Aext) {
    constexpr int KDIM = (STAGE == 1) ? CDIM : HDIM;
    constexpr int NCH  = KDIM / 32;
    const float* __restrict__ A = (STAGE == 1) ? Aext : g_h;
    const __nv_bfloat16* __restrict__ Bhp = (STAGE == 1) ? g_B1h : g_B2h;
    const __nv_bfloat16* __restrict__ Blp = (STAGE == 1) ? g_B1l : g_B2l;
    float* __restrict__ C = (STAGE == 1) ? g_Z : g_Zh;

    extern __shared__ char smem[];
    float* As = (float*)smem;                                  // [2][4608]
    __nv_bfloat16* Bhs = (__nv_bfloat16*)(smem + 36864);       // [2][3456]
    __nv_bfloat16* Bls = (__nv_bfloat16*)(smem + 50688);
    const uint32_t sb = smem_u32(smem);

    const int tid  = threadIdx.x;
    const int wid  = tid >> 5;
    const int lane = tid & 31;
    const int g    = lane >> 2;        // 0..7
    const int tg   = lane & 3;         // 0..3
    const int wm   = wid & 3;          // M warp 0..3
    const int wn   = wid >> 2;         // N warp 0..1
    const int row0 = blockIdx.x * 128;
    const int col0 = blockIdx.y * 96;

    float acc[2][6][4];
    #pragma unroll
    for (int mf = 0; mf < 2; mf++)
        #pragma unroll
        for (int nf = 0; nf < 6; nf++)
            #pragma unroll
            for (int i = 0; i < 4; i++) acc[mf][nf][i] = 0.f;

    gemm_stage<KDIM>(tid, row0, col0, 0, 0, A, Bhp, Blp, sb);
    CP_COMMIT();

    for (int kc = 0; kc < NCH; kc++) {
        if (kc + 1 < NCH) {
            gemm_stage<KDIM>(tid, row0, col0, (kc + 1) * 32, (kc + 1) & 1,
                             A, Bhp, Blp, sb);
            CP_COMMIT();
            asm volatile("cp.async.wait_group 1;" ::: "memory");
        } else {
            asm volatile("cp.async.wait_group 0;" ::: "memory");
        }
        __syncthreads();

        const int buf = kc & 1;
        const float* Ab = As + buf * 4608;
        const __nv_bfloat16* Bhb = Bhs + buf * 3456;
        const __nv_bfloat16* Blb = Bls + buf * 3456;

        #pragma unroll
        for (int ks = 0; ks < 2; ks++) {
            const int kk = ks * 16 + 2 * tg;
            uint32_t AH[2][4], AL[2][4];
            #pragma unroll
            for (int mf = 0; mf < 2; mf++) {
                int r = wm * 32 + mf * 16 + g;
                float2 v0 = *(const float2*)(Ab + r * 36 + kk);
                float2 v1 = *(const float2*)(Ab + (r + 8) * 36 + kk);
                float2 v2 = *(const float2*)(Ab + r * 36 + kk + 8);
                float2 v3 = *(const float2*)(Ab + (r + 8) * 36 + kk + 8);
                split2(v0, AH[mf][0], AL[mf][0]);
                split2(v1, AH[mf][1], AL[mf][1]);
                split2(v2, AH[mf][2], AL[mf][2]);
                split2(v3, AH[mf][3], AL[mf][3]);
            }
            #pragma unroll
            for (int nf = 0; nf < 6; nf++) {
                int n = wn * 48 + nf * 8 + g;
                const __nv_bfloat16* bp = Bhb + n * 36 + kk;
                const __nv_bfloat16* lp = Blb + n * 36 + kk;
                uint32_t bh[2] = { *(const uint32_t*)bp,
                                   *(const uint32_t*)(bp + 8) };
                uint32_t bl[2] = { *(const uint32_t*)lp,
                                   *(const uint32_t*)(lp + 8) };
                #pragma unroll
                for (int mf = 0; mf < 2; mf++) {
                    mma_bf16(acc[mf][nf], AH[mf], bh);
                    mma_bf16(acc[mf][nf], AH[mf], bl);
                    mma_bf16(acc[mf][nf], AL[mf], bh);
                }
            }
        }
        __syncthreads();
    }

    // epilogue: fp32 accumulators -> C
    #pragma unroll
    for (int mf = 0; mf < 2; mf++) {
        int row = row0 + wm * 32 + mf * 16 + g;
        #pragma unroll
        for (int nf = 0; nf < 6; nf++) {
            int col = col0 + wn * 48 + nf * 8 + 2 * tg;
            if (row < N_PTS)
                *(float2*)(C + (size_t)row * HDIM + col) =
                    make_float2(acc[mf][nf][0], acc[mf][nf][1]);
            if (row + 8 < N_PTS)
                *(float2*)(C + (size_t)(row + 8) * HDIM + col) =
                    make_float2(acc[mf][nf][2], acc[mf][nf][3]);
        }
    }
}

// ---------------- assemble stage 1:  h = relu(b1 + 3 gathered taps) --------
__global__ __launch_bounds__(256)
void assemble1_kernel(const float* __restrict__ b1) {
    int idx = blockIdx.x * 256 + threadIdx.x;      // N_PTS * 72 float4 tasks
    if (idx >= N_PTS * 72) return;
    int p = idx / 72;
    int gidx = idx - p * 72;
    int c = gidx / 24;          // tap 0..2
    int j = gidx - c * 24;      // float4 within 96
    int prev = g_prev[c * N_PTS + p];
    int next = g_next[c * N_PTS + p];
    float4 v = ((const float4*)b1)[j];
    if (prev >= 0) {
        float4 z = *(const float4*)(g_Z + (size_t)prev * HDIM + j * 4);
        v.x += z.x; v.y += z.y; v.z += z.z; v.w += z.w;
    }
    {
        float4 z = *(const float4*)(g_Z + (size_t)p * HDIM + FDIM + j * 4);
        v.x += z.x; v.y += z.y; v.z += z.z; v.w += z.w;
    }
    if (next >= 0) {
        float4 z = *(const float4*)(g_Z + (size_t)next * HDIM + 2 * FDIM + j * 4);
        v.x += z.x; v.y += z.y; v.z += z.z; v.w += z.w;
    }
    v.x = fmaxf(v.x, 0.f); v.y = fmaxf(v.y, 0.f);
    v.z = fmaxf(v.z, 0.f); v.w = fmaxf(v.w, 0.f);
    *(float4*)(g_h + (size_t)p * HDIM + c * FDIM + j * 4) = v;
}

// ------- assemble stage 2 + residual + layernorm (warp per point) ----------
__global__ __launch_bounds__(256)
void assemble2_ln_kernel(const float* __restrict__ b2,
                         const float* __restrict__ gamma,
                         const float* __restrict__ beta,
                         float* __restrict__ out) {
    int p    = (blockIdx.x * 256 + threadIdx.x) >> 5;   // warp per point
    int lane = threadIdx.x & 31;
    float4 xv[3];
    float s = 0.f, q = 0.f;
    if (lane < 24) {
        #pragma unroll
        for (int c = 0; c < 3; c++) {
            int prev = g_prev[c * N_PTS + p];
            int next = g_next[c * N_PTS + p];
            float4 v = ((const float4*)b2)[lane];
            if (prev >= 0) {
                float4 z = *(const float4*)(g_Zh + (size_t)prev * HDIM + lane * 4);
                v.x += z.x; v.y += z.y; v.z += z.z; v.w += z.w;
            }
            {
                float4 z = *(const float4*)(g_Zh + (size_t)p * HDIM + FDIM + lane * 4);
                v.x += z.x; v.y += z.y; v.z += z.z; v.w += z.w;
            }
            if (next >= 0) {
                float4 z = *(const float4*)(g_Zh + (size_t)next * HDIM + 2 * FDIM + lane * 4);
                v.x += z.x; v.y += z.y; v.z += z.z; v.w += z.w;
            }
            float4 h = *(const float4*)(g_h + (size_t)p * HDIM + c * FDIM + lane * 4);
            float4 x;
            x.x = h.x + fmaxf(v.x, 0.f);
            x.y = h.y + fmaxf(v.y, 0.f);
            x.z = h.z + fmaxf(v.z, 0.f);
            x.w = h.w + fmaxf(v.w, 0.f);
            xv[c] = x;
            s += x.x + x.y + x.z + x.w;
            q += x.x * x.x + x.y * x.y + x.z * x.z + x.w * x.w;
        }
    }
    #pragma unroll
    for (int o = 16; o > 0; o >>= 1) {
        s += __shfl_xor_sync(0xffffffffu, s, o);
        q += __shfl_xor_sync(0xffffffffu, q, o);
    }
    float mu  = s * (1.f / HDIM);
    float var = q * (1.f / HDIM) - mu * mu;
    float r   = rsqrtf(var + EPSV);
    if (lane < 24) {
        #pragma unroll
        for (int c = 0; c < 3; c++) {
            float4 gm = ((const float4*)gamma)[c * 24 + lane];
            float4 bt = ((const float4*)beta)[c * 24 + lane];
            float4 x  = xv[c];
            float4 o4;
            o4.x = (x.x - mu) * r * gm.x + bt.x;
            o4.y = (x.y - mu) * r * gm.y + bt.y;
            o4.z = (x.z - mu) * r * gm.z + bt.z;
            o4.w = (x.w - mu) * r * gm.w + bt.w;
            *(float4*)(out + (size_t)p * HDIM + c * FDIM + lane * 4) = o4;
        }
    }
}

// ---------------- index pass-through tail ----------------------------------
__global__ void copy_index_kernel(const int* __restrict__ index,
                                  float* __restrict__ out, int count) {
    int t = blockIdx.x * blockDim.x + threadIdx.x;
    if (t < count) out[t] = (float)index[t];
}

// ---------------------------------------------------------------------------
extern "C" void kernel_launch(void* const* d_in, const int* in_sizes, int n_in,
                              void* d_out, int out_size) {
    const float* X     = (const float*)d_in[0];
    const int*   index = (const int*)  d_in[1];
    const float* W1    = (const float*)d_in[2];
    const float* b1    = (const float*)d_in[3];
    const float* W2    = (const float*)d_in[4];
    const float* b2    = (const float*)d_in[5];
    const float* gamma = (const float*)d_in[6];
    const float* beta  = (const float*)d_in[7];
    float* out = (float*)d_out;

    cudaFuncSetAttribute(mma_gemm_kernel<1>,
                         cudaFuncAttributeMaxDynamicSharedMemorySize, GSM_TOTAL);
    cudaFuncSetAttribute(mma_gemm_kernel<2>,
                         cudaFuncAttributeMaxDynamicSharedMemorySize, GSM_TOTAL);

    pack_w_kernel<<<(HDIM * HDIM + 255) / 256, 256>>>(W1, W2);
    prevnext_kernel<<<(NCOLS * N_PTS + 255) / 256, 256>>>(index);

    dim3 gg((N_PTS + 127) / 128, 3);
    mma_gemm_kernel<1><<<gg, 256, GSM_TOTAL>>>(X);        // Z  = X @ B1^T
    assemble1_kernel<<<(N_PTS * 72 + 255) / 256, 256>>>(b1);
    mma_gemm_kernel<2><<<gg, 256, GSM_TOTAL>>>(nullptr);  // Zh = h @ B2^T
    assemble2_ln_kernel<<<(N_PTS * 32 + 255) / 256, 256>>>(b2, gamma, beta, out);

    int tail = out_size - N_PTS * HDIM;
    if (tail > 0) {
        if (tail > NCOLS * N_PTS) tail = NCOLS * N_PTS;
        copy_index_kernel<<<(tail + 255) / 256, 256>>>(
            index, out + (size_t)N_PTS * HDIM, tail);
    }
}